// round 1
// baseline (speedup 1.0000x reference)
#include <cuda_runtime.h>

#define Bb 32
#define Nn 1024
#define Dd 512
#define Kk 64
#define KC 80            // K + G clusters
#define ROWS (Bb * Nn)   // 32768

// scratch for softmax assignment [32768, 64]
__device__ float g_assign[ROWS * Kk];

// ---------------------------------------------------------------------------
// Kernel A: logits = x @ clusters ; BN(eval) ; softmax over 80 ; keep 64
// block: 64 rows x 80 cols, 256 threads, 4x5 microtile
// ---------------------------------------------------------------------------
__global__ __launch_bounds__(256) void assign_kernel(
    const float* __restrict__ x,      // [32768, 512]
    const float* __restrict__ W,      // [512, 80]
    const float* __restrict__ bnw, const float* __restrict__ bnb,
    const float* __restrict__ bnm, const float* __restrict__ bnv)
{
    __shared__ float As[64][33];      // 64 rows x 32 d-chunk (+pad)
    __shared__ float Bs[32][80];      // 32 d-chunk x 80 cols
    __shared__ float Ls[64][81];      // logits tile (+pad)
    __shared__ float s_sc[KC], s_tc[KC];
    __shared__ float s_m[64], s_inv[64];

    const int t = threadIdx.x;
    const int row0 = blockIdx.x * 64;

    if (t < KC) {
        float inv = rsqrtf(bnv[t] + 1e-5f);
        float sc = bnw[t] * inv;
        s_sc[t] = sc;
        s_tc[t] = bnb[t] - bnm[t] * sc;
    }

    float acc[4][5];
#pragma unroll
    for (int i = 0; i < 4; i++)
#pragma unroll
        for (int j = 0; j < 5; j++) acc[i][j] = 0.f;

    const int rg = (t >> 4) * 4;        // row group base (0..60)
    const int cg = (t & 15) * 5;        // col group base (0..75)

    for (int d0 = 0; d0 < Dd; d0 += 32) {
#pragma unroll
        for (int i = t; i < 64 * 32; i += 256)
            As[i >> 5][i & 31] = x[(row0 + (i >> 5)) * Dd + d0 + (i & 31)];
#pragma unroll
        for (int i = t; i < 32 * 80; i += 256)
            Bs[i / 80][i % 80] = W[(d0 + i / 80) * KC + (i % 80)];
        __syncthreads();

#pragma unroll
        for (int dd = 0; dd < 32; dd++) {
            float bb[5];
#pragma unroll
            for (int j = 0; j < 5; j++) bb[j] = Bs[dd][cg + j];
#pragma unroll
            for (int i = 0; i < 4; i++) {
                float a = As[rg + i][dd];
#pragma unroll
                for (int j = 0; j < 5; j++) acc[i][j] = fmaf(a, bb[j], acc[i][j]);
            }
        }
        __syncthreads();
    }

    // BN fold + stage logits
#pragma unroll
    for (int i = 0; i < 4; i++)
#pragma unroll
        for (int j = 0; j < 5; j++)
            Ls[rg + i][cg + j] = acc[i][j] * s_sc[cg + j] + s_tc[cg + j];
    __syncthreads();

    // row max + expsum (one thread per row)
    if (t < 64) {
        float m = -1e30f;
#pragma unroll
        for (int j = 0; j < KC; j++) m = fmaxf(m, Ls[t][j]);
        float s = 0.f;
#pragma unroll
        for (int j = 0; j < KC; j++) s += __expf(Ls[t][j] - m);
        s_m[t] = m;
        s_inv[t] = 1.f / s;
    }
    __syncthreads();

    // coalesced write of assignment[:, :64]
#pragma unroll
    for (int i = t; i < 64 * 64; i += 256) {
        int r = i >> 6, k = i & 63;
        g_assign[(row0 + r) * Kk + k] = __expf(Ls[r][k] - s_m[r]) * s_inv[r];
    }
}

// ---------------------------------------------------------------------------
// Kernel B: vlad[b,d,k] = sum_n a[b,n,k]*x[b,n,d] - a_sum[b,k]*c2[d,k]
// block: (batch b, 64-wide d tile) -> 64x64 output, 256 threads, 4x4 microtile
// ---------------------------------------------------------------------------
__global__ __launch_bounds__(256) void vlad_kernel(
    const float* __restrict__ x,     // [32768, 512]
    const float* __restrict__ c2,    // [512, 64]
    float* __restrict__ out)         // [32, 512*64]
{
    __shared__ float a_s[32][68];
    __shared__ float x_s[32][68];
    __shared__ float asum_s[64];

    const int t = threadIdx.x;
    const int b = blockIdx.y;
    const int d0 = blockIdx.x * 64;

    float acc[4][4];
#pragma unroll
    for (int i = 0; i < 4; i++)
#pragma unroll
        for (int j = 0; j < 4; j++) acc[i][j] = 0.f;
    float asum = 0.f;

    const int dg = (t >> 4) * 4;
    const int kg = (t & 15) * 4;

    for (int n0 = 0; n0 < Nn; n0 += 32) {
#pragma unroll
        for (int i = t; i < 32 * 64; i += 256) {
            int r = i >> 6, c = i & 63;
            a_s[r][c] = g_assign[((b * Nn) + n0 + r) * Kk + c];
            x_s[r][c] = x[((b * Nn) + n0 + r) * Dd + d0 + c];
        }
        __syncthreads();

        if (t < 64) {
#pragma unroll
            for (int nn = 0; nn < 32; nn++) asum += a_s[nn][t];
        }
#pragma unroll
        for (int nn = 0; nn < 32; nn++) {
            float4 xa = *reinterpret_cast<const float4*>(&x_s[nn][dg]);
            float4 aa = *reinterpret_cast<const float4*>(&a_s[nn][kg]);
            float xv[4] = {xa.x, xa.y, xa.z, xa.w};
            float av[4] = {aa.x, aa.y, aa.z, aa.w};
#pragma unroll
            for (int i = 0; i < 4; i++)
#pragma unroll
                for (int j = 0; j < 4; j++)
                    acc[i][j] = fmaf(xv[i], av[j], acc[i][j]);
        }
        __syncthreads();
    }

    if (t < 64) asum_s[t] = asum;
    __syncthreads();

#pragma unroll
    for (int i = 0; i < 4; i++) {
        int d = d0 + dg + i;
#pragma unroll
        for (int j = 0; j < 4; j++) {
            int k = kg + j;
            out[b * (Dd * Kk) + d * Kk + k] = acc[i][j] - asum_s[k] * c2[d * Kk + k];
        }
    }
}

// ---------------------------------------------------------------------------
// Kernel C: composed double L2-normalize per batch (one block per batch)
// scale = 1/(sqrt(s+eps) * sqrt(s/(s+eps)+eps))
// ---------------------------------------------------------------------------
__global__ __launch_bounds__(1024) void norm_kernel(float* __restrict__ out)
{
    const int b = blockIdx.x;
    const int t = threadIdx.x;
    float* p = out + b * (Dd * Kk);

    float s = 0.f;
#pragma unroll 8
    for (int i = t; i < Dd * Kk; i += 1024) {
        float v = p[i];
        s = fmaf(v, v, s);
    }

    __shared__ float red[32];
#pragma unroll
    for (int off = 16; off > 0; off >>= 1) s += __shfl_xor_sync(0xffffffffu, s, off);
    if ((t & 31) == 0) red[t >> 5] = s;
    __syncthreads();

    __shared__ float scale_s;
    if (t < 32) {
        float v = red[t];
#pragma unroll
        for (int off = 16; off > 0; off >>= 1) v += __shfl_xor_sync(0xffffffffu, v, off);
        if (t == 0) {
            float s1 = v + 1e-12f;
            float n1 = sqrtf(s1);
            float s2 = v / s1 + 1e-12f;   // sum of squares after first normalize
            scale_s = 1.f / (n1 * sqrtf(s2));
        }
    }
    __syncthreads();

    float sc = scale_s;
#pragma unroll 8
    for (int i = t; i < Dd * Kk; i += 1024) p[i] *= sc;
}

// ---------------------------------------------------------------------------
extern "C" void kernel_launch(void* const* d_in, const int* in_sizes, int n_in,
                              void* d_out, int out_size)
{
    const float* x   = (const float*)d_in[0];   // [32,1024,512]
    const float* W   = (const float*)d_in[1];   // [512,80]
    const float* c2  = (const float*)d_in[2];   // [1,512,64]
    const float* bnw = (const float*)d_in[3];
    const float* bnb = (const float*)d_in[4];
    const float* bnm = (const float*)d_in[5];
    const float* bnv = (const float*)d_in[6];
    float* out = (float*)d_out;                 // [32, 32768]

    assign_kernel<<<ROWS / 64, 256>>>(x, W, bnw, bnb, bnm, bnv);
    vlad_kernel<<<dim3(Dd / 64, Bb), 256>>>(x, c2, out);
    norm_kernel<<<Bb, 1024>>>(out);
}

// round 2
// speedup vs baseline: 2.2134x; 2.2134x over previous
#include <cuda_runtime.h>
#include <cstdint>

#define Bb 32
#define Nn 1024
#define Dd 512
#define Kk 64
#define KC 80            // K + G clusters
#define ROWS (Bb * Nn)   // 32768

// scratch: softmax assignment [32768, 64] and per-assign-block column sums
__device__ float g_assign[ROWS * Kk];
__device__ float g_asum_part[256 * Kk];   // 256 assign blocks x 64 cols

// ---------------------------------------------------------------------------
// helpers: tf32 round + m16n8k8 tf32 mma
// ---------------------------------------------------------------------------
__device__ __forceinline__ float to_tf32(float x) {
    uint32_t r;
    asm("cvt.rna.tf32.f32 %0, %1;" : "=r"(r) : "f"(x));
    return __uint_as_float(r);
}

__device__ __forceinline__ void mma8(float* d, const uint32_t* a,
                                     uint32_t b0, uint32_t b1) {
    asm volatile(
        "mma.sync.aligned.m16n8k8.row.col.f32.tf32.tf32.f32 "
        "{%0,%1,%2,%3}, {%4,%5,%6,%7}, {%8,%9}, {%0,%1,%2,%3};"
        : "+f"(d[0]), "+f"(d[1]), "+f"(d[2]), "+f"(d[3])
        : "r"(a[0]), "r"(a[1]), "r"(a[2]), "r"(a[3]), "r"(b0), "r"(b1));
}

// ---------------------------------------------------------------------------
// Kernel A: logits = x @ clusters ; BN(eval) ; softmax over 80 ; keep 64.
// Block tile 128 rows x 80 cols, 8 warps (4M x 2N), warp tile 32x40.
// ---------------------------------------------------------------------------
union AssignSmem {
    struct { float As[128][36]; float Bs[32][88]; } g;   // GEMM staging
    struct { float Ls[128][81]; float inv[128]; float red[256]; } s; // softmax
};

__global__ __launch_bounds__(256) void assign_kernel(
    const float* __restrict__ x,      // [32768, 512]
    const float* __restrict__ W,      // [512, 80]
    const float* __restrict__ bnw, const float* __restrict__ bnb,
    const float* __restrict__ bnm, const float* __restrict__ bnv)
{
    __shared__ AssignSmem sm;
    __shared__ float s_sc[KC], s_tc[KC];

    const int t = threadIdx.x;
    const int lane = t & 31;
    const int wid = t >> 5;
    const int warpM = wid & 3;       // 0..3 -> 32-row stripe
    const int warpN = wid >> 2;      // 0..1 -> 40-col stripe
    const int g   = lane >> 2;       // 0..7
    const int tig = lane & 3;        // 0..3
    const int row0 = blockIdx.x * 128;

    if (t < KC) {
        float iv = rsqrtf(bnv[t] + 1e-5f);
        float sc = bnw[t] * iv;
        s_sc[t] = sc;
        s_tc[t] = bnb[t] - bnm[t] * sc;
    }

    float acc[2][5][4];
#pragma unroll
    for (int a = 0; a < 2; a++)
#pragma unroll
        for (int b = 0; b < 5; b++)
#pragma unroll
            for (int c = 0; c < 4; c++) acc[a][b][c] = 0.f;

    for (int kt = 0; kt < Dd; kt += 32) {
        // stage As: 128 rows x 32 k  (tf32-rounded)
#pragma unroll
        for (int i = t; i < 1024; i += 256) {
            int r = i >> 3, c4 = (i & 7) << 2;
            float4 v = *reinterpret_cast<const float4*>(
                &x[(size_t)(row0 + r) * Dd + kt + c4]);
            float* dst = &sm.g.As[r][c4];
            dst[0] = to_tf32(v.x); dst[1] = to_tf32(v.y);
            dst[2] = to_tf32(v.z); dst[3] = to_tf32(v.w);
        }
        // stage Bs: 32 k x 80 cols
#pragma unroll
        for (int i = t; i < 640; i += 256) {
            int r = i / 20, c4 = (i % 20) << 2;
            float4 v = *reinterpret_cast<const float4*>(
                &W[(size_t)(kt + r) * KC + c4]);
            float* dst = &sm.g.Bs[r][c4];
            dst[0] = to_tf32(v.x); dst[1] = to_tf32(v.y);
            dst[2] = to_tf32(v.z); dst[3] = to_tf32(v.w);
        }
        __syncthreads();

#pragma unroll
        for (int ks = 0; ks < 4; ks++) {
            const int kk = ks << 3;
            uint32_t af[2][4];
#pragma unroll
            for (int mf = 0; mf < 2; mf++) {
                const int rb = warpM * 32 + mf * 16 + g;
                af[mf][0] = __float_as_uint(sm.g.As[rb    ][kk + tig    ]);
                af[mf][1] = __float_as_uint(sm.g.As[rb + 8][kk + tig    ]);
                af[mf][2] = __float_as_uint(sm.g.As[rb    ][kk + tig + 4]);
                af[mf][3] = __float_as_uint(sm.g.As[rb + 8][kk + tig + 4]);
            }
#pragma unroll
            for (int nf = 0; nf < 5; nf++) {
                const int cb = warpN * 40 + nf * 8 + g;
                uint32_t b0 = __float_as_uint(sm.g.Bs[kk + tig    ][cb]);
                uint32_t b1 = __float_as_uint(sm.g.Bs[kk + tig + 4][cb]);
                mma8(acc[0][nf], af[0], b0, b1);
                mma8(acc[1][nf], af[1], b0, b1);
            }
        }
        __syncthreads();
    }

    // BN fold + stage logits (union reuse: GEMM tiles dead now)
#pragma unroll
    for (int mf = 0; mf < 2; mf++)
#pragma unroll
        for (int nf = 0; nf < 5; nf++)
#pragma unroll
            for (int c = 0; c < 4; c++) {
                int row = warpM * 32 + mf * 16 + g + ((c >> 1) << 3);
                int col = warpN * 40 + nf * 8 + 2 * tig + (c & 1);
                sm.s.Ls[row][col] = fmaf(acc[mf][nf][c], s_sc[col], s_tc[col]);
            }
    __syncthreads();

    // per-row softmax over 80 cols, keep exp of first 64 in Ls
    if (t < 128) {
        float m = -1e30f;
#pragma unroll
        for (int j = 0; j < KC; j++) m = fmaxf(m, sm.s.Ls[t][j]);
        float ssum = 0.f;
#pragma unroll
        for (int j = 0; j < KC; j++) {
            float e = __expf(sm.s.Ls[t][j] - m);
            ssum += e;
            if (j < Kk) sm.s.Ls[t][j] = e;
        }
        sm.s.inv[t] = 1.f / ssum;
    }
    __syncthreads();

    // coalesced write + per-column partial sums (deterministic, no atomics)
    float partial = 0.f;
#pragma unroll
    for (int i = t; i < 128 * Kk; i += 256) {
        int r = i >> 6, k = i & 63;
        float e = sm.s.Ls[r][k] * sm.s.inv[r];
        g_assign[(size_t)(row0 + r) * Kk + k] = e;
        partial += e;                     // k constant per thread
    }
    sm.s.red[t] = partial;
    __syncthreads();
    if (t < 64)
        g_asum_part[blockIdx.x * Kk + t] =
            sm.s.red[t] + sm.s.red[t + 64] + sm.s.red[t + 128] + sm.s.red[t + 192];
}

// ---------------------------------------------------------------------------
// Kernel B: O[k][d] = sum_n a[n,k] * x[n,d]  -  asum[k]*c2[d,k]
// m = k (64), n = d (64-tile), kdim = n tokens. B = x natural layout.
// Block: 128 threads (2 kwarps x 2 dwarps), warp tile 32k x 32d.
// ---------------------------------------------------------------------------
__global__ __launch_bounds__(128) void vlad_kernel(
    const float* __restrict__ x,     // [32768, 512]
    const float* __restrict__ c2,    // [512, 64]
    float* __restrict__ out)         // [32, 512*64]
{
    __shared__ float x_s[32][72];    // [n][d]   8*tig+g banks -> conflict-free
    __shared__ float a_sT[64][35];   // [k][n]   2-way worst case
    __shared__ float asum_s[64];

    const int t = threadIdx.x;
    const int lane = t & 31;
    const int wid = t >> 5;
    const int warpM = wid & 1;       // k stripe
    const int warpN = wid >> 1;      // d stripe
    const int g   = lane >> 2;
    const int tig = lane & 3;
    const int b  = blockIdx.y;
    const int d0 = blockIdx.x * 64;

    if (t < 64) {
        float s = 0.f;
#pragma unroll
        for (int j = 0; j < 8; j++)
            s += g_asum_part[((b << 3) + j) * Kk + t];
        asum_s[t] = s;
    }

    float acc[2][4][4];
#pragma unroll
    for (int a = 0; a < 2; a++)
#pragma unroll
        for (int b2 = 0; b2 < 4; b2++)
#pragma unroll
            for (int c = 0; c < 4; c++) acc[a][b2][c] = 0.f;

    const float* xb = x + (size_t)b * Nn * Dd + d0;
    const float* ab = g_assign + (size_t)b * Nn * Kk;

    for (int n0 = 0; n0 < Nn; n0 += 32) {
        // x tile [32 n][64 d], natural layout
#pragma unroll
        for (int i = t; i < 512; i += 128) {
            int nn = i >> 4, dq = (i & 15) << 2;
            float4 v = *reinterpret_cast<const float4*>(
                &xb[(size_t)(n0 + nn) * Dd + dq]);
            float* dst = &x_s[nn][dq];
            dst[0] = to_tf32(v.x); dst[1] = to_tf32(v.y);
            dst[2] = to_tf32(v.z); dst[3] = to_tf32(v.w);
        }
        // a tile [32 n][64 k] -> transposed a_sT[k][n]
#pragma unroll
        for (int i = t; i < 512; i += 128) {
            int nn = i >> 4, kq = (i & 15) << 2;
            float4 v = *reinterpret_cast<const float4*>(
                &ab[(size_t)(n0 + nn) * Kk + kq]);
            a_sT[kq    ][nn] = to_tf32(v.x);
            a_sT[kq + 1][nn] = to_tf32(v.y);
            a_sT[kq + 2][nn] = to_tf32(v.z);
            a_sT[kq + 3][nn] = to_tf32(v.w);
        }
        __syncthreads();

#pragma unroll
        for (int ks = 0; ks < 4; ks++) {
            const int kk = ks << 3;
            uint32_t af[2][4];
#pragma unroll
            for (int mf = 0; mf < 2; mf++) {
                const int rb = warpM * 32 + mf * 16 + g;
                af[mf][0] = __float_as_uint(a_sT[rb    ][kk + tig    ]);
                af[mf][1] = __float_as_uint(a_sT[rb + 8][kk + tig    ]);
                af[mf][2] = __float_as_uint(a_sT[rb    ][kk + tig + 4]);
                af[mf][3] = __float_as_uint(a_sT[rb + 8][kk + tig + 4]);
            }
#pragma unroll
            for (int nf = 0; nf < 4; nf++) {
                const int cb = warpN * 32 + nf * 8 + g;
                uint32_t b0 = __float_as_uint(x_s[kk + tig    ][cb]);
                uint32_t b1 = __float_as_uint(x_s[kk + tig + 4][cb]);
                mma8(acc[0][nf], af[0], b0, b1);
                mma8(acc[1][nf], af[1], b0, b1);
            }
        }
        __syncthreads();
    }

    // epilogue: D[m=k][n=d]; subtract asum[k]*c2[d,k]; stores are sector-full
    float* ob = out + (size_t)b * (Dd * Kk);
#pragma unroll
    for (int mf = 0; mf < 2; mf++)
#pragma unroll
        for (int nf = 0; nf < 4; nf++)
#pragma unroll
            for (int c = 0; c < 4; c++) {
                int k = warpM * 32 + mf * 16 + g + ((c >> 1) << 3);
                int d = d0 + warpN * 32 + nf * 8 + 2 * tig + (c & 1);
                ob[(size_t)d * Kk + k] =
                    acc[mf][nf][c] - asum_s[k] * c2[(size_t)d * Kk + k];
            }
}

// ---------------------------------------------------------------------------
// Kernel C: composed double L2-normalize per batch.
// scale = 1/(sqrt(s+eps) * sqrt(s/(s+eps)+eps))
// ---------------------------------------------------------------------------
__global__ __launch_bounds__(1024) void norm_kernel(float* __restrict__ out)
{
    const int b = blockIdx.x;
    const int t = threadIdx.x;
    float4* p = reinterpret_cast<float4*>(out + (size_t)b * (Dd * Kk));

    float s = 0.f;
#pragma unroll 4
    for (int i = t; i < 8192; i += 1024) {
        float4 v = p[i];
        s = fmaf(v.x, v.x, s); s = fmaf(v.y, v.y, s);
        s = fmaf(v.z, v.z, s); s = fmaf(v.w, v.w, s);
    }

    __shared__ float red[32];
#pragma unroll
    for (int off = 16; off > 0; off >>= 1) s += __shfl_xor_sync(0xffffffffu, s, off);
    if ((t & 31) == 0) red[t >> 5] = s;
    __syncthreads();

    __shared__ float scale_s;
    if (t < 32) {
        float v = red[t];
#pragma unroll
        for (int off = 16; off > 0; off >>= 1) v += __shfl_xor_sync(0xffffffffu, v, off);
        if (t == 0) {
            float s1 = v + 1e-12f;
            float n1 = sqrtf(s1);
            float s2 = v / s1 + 1e-12f;
            scale_s = 1.f / (n1 * sqrtf(s2));
        }
    }
    __syncthreads();

    float sc = scale_s;
#pragma unroll 4
    for (int i = t; i < 8192; i += 1024) {
        float4 v = p[i];
        v.x *= sc; v.y *= sc; v.z *= sc; v.w *= sc;
        p[i] = v;
    }
}

// ---------------------------------------------------------------------------
extern "C" void kernel_launch(void* const* d_in, const int* in_sizes, int n_in,
                              void* d_out, int out_size)
{
    const float* x   = (const float*)d_in[0];   // [32,1024,512]
    const float* W   = (const float*)d_in[1];   // [512,80]
    const float* c2  = (const float*)d_in[2];   // [1,512,64]
    const float* bnw = (const float*)d_in[3];
    const float* bnb = (const float*)d_in[4];
    const float* bnm = (const float*)d_in[5];
    const float* bnv = (const float*)d_in[6];
    float* out = (float*)d_out;                 // [32, 32768]

    assign_kernel<<<ROWS / 128, 256>>>(x, W, bnw, bnb, bnm, bnv);
    vlad_kernel<<<dim3(Dd / 64, Bb), 128>>>(x, c2, out);
    norm_kernel<<<Bb, 1024>>>(out);
}

// round 3
// speedup vs baseline: 2.3805x; 1.0755x over previous
#include <cuda_runtime.h>
#include <cstdint>

#define Bb 32
#define Nn 1024
#define Dd 512
#define Kk 64
#define KC 80            // K + G clusters
#define ROWS (Bb * Nn)   // 32768

// scratch: softmax assignment, per-block column sums, per-block sumsq partials
__device__ float g_assign[ROWS * Kk];
__device__ float g_asum_part[256 * Kk];
__device__ float g_ssq_part[Bb * 8];

// ---------------------------------------------------------------------------
__device__ __forceinline__ float to_tf32(float x) {
    uint32_t r;
    asm("cvt.rna.tf32.f32 %0, %1;" : "=r"(r) : "f"(x));
    return __uint_as_float(r);
}

__device__ __forceinline__ void mma8(float* d, const uint32_t* a,
                                     uint32_t b0, uint32_t b1) {
    asm volatile(
        "mma.sync.aligned.m16n8k8.row.col.f32.tf32.tf32.f32 "
        "{%0,%1,%2,%3}, {%4,%5,%6,%7}, {%8,%9}, {%0,%1,%2,%3};"
        : "+f"(d[0]), "+f"(d[1]), "+f"(d[2]), "+f"(d[3])
        : "r"(a[0]), "r"(a[1]), "r"(a[2]), "r"(a[3]), "r"(b0), "r"(b1));
}

// ---------------------------------------------------------------------------
// Kernel A: logits = x @ clusters ; BN(eval) ; softmax over 80 ; keep 64.
// Block tile 128x80, 8 warps (4Mx2N), warp tile 32x40. Register-prefetch
// pipeline: LDG(chunk c+1) issued before MMA(chunk c).
// ---------------------------------------------------------------------------
union AssignSmem {
    struct { float As[128][36]; float Bs[32][88]; } g;
    struct { float Ls[128][81]; float inv[128]; float red[256]; } s;
};

__global__ __launch_bounds__(256, 2) void assign_kernel(
    const float* __restrict__ x,      // [32768, 512]
    const float* __restrict__ W,      // [512, 80]
    const float* __restrict__ bnw, const float* __restrict__ bnb,
    const float* __restrict__ bnm, const float* __restrict__ bnv)
{
    __shared__ AssignSmem sm;
    __shared__ float s_sc[KC], s_tc[KC];

    const int t = threadIdx.x;
    const int lane = t & 31;
    const int wid = t >> 5;
    const int warpM = wid & 3;
    const int warpN = wid >> 2;
    const int g   = lane >> 2;
    const int tig = lane & 3;
    const int row0 = blockIdx.x * 128;

    if (t < KC) {
        float iv = rsqrtf(bnv[t] + 1e-5f);
        float sc = bnw[t] * iv;
        s_sc[t] = sc;
        s_tc[t] = bnb[t] - bnm[t] * sc;
    }

    float acc[2][5][4];
#pragma unroll
    for (int a = 0; a < 2; a++)
#pragma unroll
        for (int b = 0; b < 5; b++)
#pragma unroll
            for (int c = 0; c < 4; c++) acc[a][b][c] = 0.f;

    // prefetch registers
    float4 pa[4];
    float4 pb[3];
    const int ar = t >> 3, ac4 = (t & 7) << 2;           // As: row step 32/iter
    const int br0 = t / 20,  bc4 = (t % 20) << 2;        // Bs indices per j

    // ---- prologue: LDG chunk 0
#pragma unroll
    for (int j = 0; j < 4; j++)
        pa[j] = *reinterpret_cast<const float4*>(
            &x[(size_t)(row0 + ar + j * 32) * Dd + ac4]);
#pragma unroll
    for (int j = 0; j < 3; j++) {
        int i = t + j * 256;
        if (i < 640)
            pb[j] = *reinterpret_cast<const float4*>(
                &W[(size_t)(i / 20) * KC + ((i % 20) << 2)]);
    }

    for (int c = 0; c < 16; c++) {
        // ---- STS with tf32 rounding
#pragma unroll
        for (int j = 0; j < 4; j++) {
            float* dst = &sm.g.As[ar + j * 32][ac4];
            dst[0] = to_tf32(pa[j].x); dst[1] = to_tf32(pa[j].y);
            dst[2] = to_tf32(pa[j].z); dst[3] = to_tf32(pa[j].w);
        }
#pragma unroll
        for (int j = 0; j < 3; j++) {
            int i = t + j * 256;
            if (i < 640) {
                float* dst = &sm.g.Bs[i / 20][(i % 20) << 2];
                dst[0] = to_tf32(pb[j].x); dst[1] = to_tf32(pb[j].y);
                dst[2] = to_tf32(pb[j].z); dst[3] = to_tf32(pb[j].w);
            }
        }
        __syncthreads();

        // ---- LDG chunk c+1 (latency hidden behind MMA phase)
        if (c < 15) {
            const int kt = (c + 1) * 32;
#pragma unroll
            for (int j = 0; j < 4; j++)
                pa[j] = *reinterpret_cast<const float4*>(
                    &x[(size_t)(row0 + ar + j * 32) * Dd + kt + ac4]);
#pragma unroll
            for (int j = 0; j < 3; j++) {
                int i = t + j * 256;
                if (i < 640)
                    pb[j] = *reinterpret_cast<const float4*>(
                        &W[(size_t)(kt + i / 20) * KC + ((i % 20) << 2)]);
            }
        }

        // ---- MMA phase over the 32-deep chunk
#pragma unroll
        for (int ks = 0; ks < 4; ks++) {
            const int kk = ks << 3;
            uint32_t af[2][4];
#pragma unroll
            for (int mf = 0; mf < 2; mf++) {
                const int rb = warpM * 32 + mf * 16 + g;
                af[mf][0] = __float_as_uint(sm.g.As[rb    ][kk + tig    ]);
                af[mf][1] = __float_as_uint(sm.g.As[rb + 8][kk + tig    ]);
                af[mf][2] = __float_as_uint(sm.g.As[rb    ][kk + tig + 4]);
                af[mf][3] = __float_as_uint(sm.g.As[rb + 8][kk + tig + 4]);
            }
#pragma unroll
            for (int nf = 0; nf < 5; nf++) {
                const int cb = warpN * 40 + nf * 8 + g;
                uint32_t b0 = __float_as_uint(sm.g.Bs[kk + tig    ][cb]);
                uint32_t b1 = __float_as_uint(sm.g.Bs[kk + tig + 4][cb]);
                mma8(acc[0][nf], af[0], b0, b1);
                mma8(acc[1][nf], af[1], b0, b1);
            }
        }
        __syncthreads();
    }

    // BN fold + stage logits in union
#pragma unroll
    for (int mf = 0; mf < 2; mf++)
#pragma unroll
        for (int nf = 0; nf < 5; nf++)
#pragma unroll
            for (int c = 0; c < 4; c++) {
                int row = warpM * 32 + mf * 16 + g + ((c >> 1) << 3);
                int col = warpN * 40 + nf * 8 + 2 * tig + (c & 1);
                sm.s.Ls[row][col] = fmaf(acc[mf][nf][c], s_sc[col], s_tc[col]);
            }
    __syncthreads();

    // per-row softmax over 80 cols
    if (t < 128) {
        float m = -1e30f;
#pragma unroll
        for (int j = 0; j < KC; j++) m = fmaxf(m, sm.s.Ls[t][j]);
        float ssum = 0.f;
#pragma unroll
        for (int j = 0; j < KC; j++) {
            float e = __expf(sm.s.Ls[t][j] - m);
            ssum += e;
            if (j < Kk) sm.s.Ls[t][j] = e;
        }
        sm.s.inv[t] = 1.f / ssum;
    }
    __syncthreads();

    // coalesced write + per-column partial sums (deterministic)
    float partial = 0.f;
#pragma unroll
    for (int i = t; i < 128 * Kk; i += 256) {
        int r = i >> 6, k = i & 63;
        float e = sm.s.Ls[r][k] * sm.s.inv[r];
        g_assign[(size_t)(row0 + r) * Kk + k] = e;
        partial += e;
    }
    sm.s.red[t] = partial;
    __syncthreads();
    if (t < 64)
        g_asum_part[blockIdx.x * Kk + t] =
            sm.s.red[t] + sm.s.red[t + 64] + sm.s.red[t + 128] + sm.s.red[t + 192];
}

// ---------------------------------------------------------------------------
// Kernel B: O[k][d] = sum_n a[n,k]*x[n,d] - asum[k]*c2[d,k].  256 threads,
// 8 warps (4k x 2d), warp tile 16k x 32d, register-prefetch pipeline.
// Also emits per-block sum-of-squares partials for the norm pass.
// ---------------------------------------------------------------------------
__global__ __launch_bounds__(256, 2) void vlad_kernel(
    const float* __restrict__ x,     // [32768, 512]
    const float* __restrict__ c2,    // [512, 64]
    float* __restrict__ out)         // [32, 512*64]
{
    __shared__ float x_s[32][72];
    __shared__ float a_sT[64][35];
    __shared__ float asum_s[64];
    __shared__ float redsq[8];

    const int t = threadIdx.x;
    const int lane = t & 31;
    const int wid = t >> 5;
    const int warpM = wid & 3;        // k stripe (16 rows)
    const int warpN = wid >> 2;       // d stripe (32 cols)
    const int g   = lane >> 2;
    const int tig = lane & 3;
    const int b  = blockIdx.y;
    const int d0 = blockIdx.x * 64;

    if (t < 64) {
        float s = 0.f;
#pragma unroll
        for (int j = 0; j < 8; j++)
            s += g_asum_part[((b << 3) + j) * Kk + t];
        asum_s[t] = s;
    }

    float acc[4][4];
#pragma unroll
    for (int i = 0; i < 4; i++)
#pragma unroll
        for (int j = 0; j < 4; j++) acc[i][j] = 0.f;

    const float* xb = x + (size_t)b * Nn * Dd + d0;
    const float* ab = g_assign + (size_t)b * Nn * Kk;

    const int xn = t >> 4, xq = (t & 15) << 2;   // x/a tile indices (j offsets rows)
    float4 px[2], pq[2];

    // prologue: LDG chunk 0
#pragma unroll
    for (int j = 0; j < 2; j++) {
        px[j] = *reinterpret_cast<const float4*>(&xb[(size_t)(xn + j * 16) * Dd + xq]);
        pq[j] = *reinterpret_cast<const float4*>(&ab[(size_t)(xn + j * 16) * Kk + xq]);
    }

    for (int c = 0; c < 32; c++) {
        // STS with tf32 rounding (a transposed)
#pragma unroll
        for (int j = 0; j < 2; j++) {
            float* dst = &x_s[xn + j * 16][xq];
            dst[0] = to_tf32(px[j].x); dst[1] = to_tf32(px[j].y);
            dst[2] = to_tf32(px[j].z); dst[3] = to_tf32(px[j].w);
            int nn = xn + j * 16;
            a_sT[xq    ][nn] = to_tf32(pq[j].x);
            a_sT[xq + 1][nn] = to_tf32(pq[j].y);
            a_sT[xq + 2][nn] = to_tf32(pq[j].z);
            a_sT[xq + 3][nn] = to_tf32(pq[j].w);
        }
        __syncthreads();

        if (c < 31) {
            const int n1 = (c + 1) * 32;
#pragma unroll
            for (int j = 0; j < 2; j++) {
                px[j] = *reinterpret_cast<const float4*>(
                    &xb[(size_t)(n1 + xn + j * 16) * Dd + xq]);
                pq[j] = *reinterpret_cast<const float4*>(
                    &ab[(size_t)(n1 + xn + j * 16) * Kk + xq]);
            }
        }

#pragma unroll
        for (int ks = 0; ks < 4; ks++) {
            const int kk = ks << 3;
            uint32_t af[4];
            const int rb = warpM * 16 + g;
            af[0] = __float_as_uint(a_sT[rb    ][kk + tig    ]);
            af[1] = __float_as_uint(a_sT[rb + 8][kk + tig    ]);
            af[2] = __float_as_uint(a_sT[rb    ][kk + tig + 4]);
            af[3] = __float_as_uint(a_sT[rb + 8][kk + tig + 4]);
#pragma unroll
            for (int nf = 0; nf < 4; nf++) {
                const int cb = warpN * 32 + nf * 8 + g;
                uint32_t b0 = __float_as_uint(x_s[kk + tig    ][cb]);
                uint32_t b1 = __float_as_uint(x_s[kk + tig + 4][cb]);
                mma8(acc[nf], af, b0, b1);
            }
        }
        __syncthreads();
    }

    // epilogue: correction + store + sumsq partial
    float* ob = out + (size_t)b * (Dd * Kk);
    float ssq = 0.f;
#pragma unroll
    for (int nf = 0; nf < 4; nf++)
#pragma unroll
        for (int c = 0; c < 4; c++) {
            int k = warpM * 16 + g + ((c >> 1) << 3);
            int d = d0 + warpN * 32 + nf * 8 + 2 * tig + (c & 1);
            float v = acc[nf][c] - asum_s[k] * c2[(size_t)d * Kk + k];
            ob[(size_t)d * Kk + k] = v;
            ssq = fmaf(v, v, ssq);
        }
#pragma unroll
    for (int off = 16; off > 0; off >>= 1)
        ssq += __shfl_xor_sync(0xffffffffu, ssq, off);
    if (lane == 0) redsq[wid] = ssq;
    __syncthreads();
    if (t == 0) {
        float s = 0.f;
#pragma unroll
        for (int j = 0; j < 8; j++) s += redsq[j];
        g_ssq_part[b * 8 + blockIdx.x] = s;
    }
}

// ---------------------------------------------------------------------------
// Kernel C: pure scale pass using vlad's sumsq partials.
// composed double-normalize scale = 1/(sqrt(s+eps)*sqrt(s/(s+eps)+eps))
// ---------------------------------------------------------------------------
__global__ __launch_bounds__(1024) void norm_kernel(float* __restrict__ out)
{
    const int b = blockIdx.x;
    const int t = threadIdx.x;
    __shared__ float scale_s;

    if (t == 0) {
        float v = 0.f;
#pragma unroll
        for (int j = 0; j < 8; j++) v += g_ssq_part[b * 8 + j];
        float s1 = v + 1e-12f;
        float n1 = sqrtf(s1);
        float s2 = v / s1 + 1e-12f;
        scale_s = 1.f / (n1 * sqrtf(s2));
    }
    __syncthreads();

    float sc = scale_s;
    float4* p = reinterpret_cast<float4*>(out + (size_t)b * (Dd * Kk));
#pragma unroll 4
    for (int i = t; i < 8192; i += 1024) {
        float4 v = p[i];
        v.x *= sc; v.y *= sc; v.z *= sc; v.w *= sc;
        p[i] = v;
    }
}

// ---------------------------------------------------------------------------
extern "C" void kernel_launch(void* const* d_in, const int* in_sizes, int n_in,
                              void* d_out, int out_size)
{
    const float* x   = (const float*)d_in[0];   // [32,1024,512]
    const float* W   = (const float*)d_in[1];   // [512,80]
    const float* c2  = (const float*)d_in[2];   // [1,512,64]
    const float* bnw = (const float*)d_in[3];
    const float* bnb = (const float*)d_in[4];
    const float* bnm = (const float*)d_in[5];
    const float* bnv = (const float*)d_in[6];
    float* out = (float*)d_out;                 // [32, 32768]

    assign_kernel<<<ROWS / 128, 256>>>(x, W, bnw, bnb, bnm, bnv);
    vlad_kernel<<<dim3(Dd / 64, Bb), 256>>>(x, c2, out);
    norm_kernel<<<Bb, 1024>>>(out);
}

// round 4
// speedup vs baseline: 2.8066x; 1.1790x over previous
#include <cuda_runtime.h>
#include <cstdint>

#define Bb 32
#define Nn 1024
#define Dd 512
#define Kk 64
#define KC 80            // K + G clusters
#define ROWS (Bb * Nn)   // 32768

// g_assign stored TRANSPOSED: [b][k][n]  (b*Kk + k)*Nn + n, tf32-pre-rounded
__device__ float g_assign[ROWS * Kk];
__device__ float g_asum_part[256 * Kk];
__device__ float g_ssq_part[Bb * 8];

// ---------------------------------------------------------------------------
__device__ __forceinline__ float to_tf32(float x) {
    uint32_t r;
    asm("cvt.rna.tf32.f32 %0, %1;" : "=r"(r) : "f"(x));
    return __uint_as_float(r);
}

__device__ __forceinline__ void mma8(float* d, const uint32_t* a,
                                     uint32_t b0, uint32_t b1) {
    asm volatile(
        "mma.sync.aligned.m16n8k8.row.col.f32.tf32.tf32.f32 "
        "{%0,%1,%2,%3}, {%4,%5,%6,%7}, {%8,%9}, {%0,%1,%2,%3};"
        : "+f"(d[0]), "+f"(d[1]), "+f"(d[2]), "+f"(d[3])
        : "r"(a[0]), "r"(a[1]), "r"(a[2]), "r"(a[3]), "r"(b0), "r"(b1));
}

__device__ __forceinline__ void cp16(void* sdst, const void* gsrc) {
    uint32_t s = (uint32_t)__cvta_generic_to_shared(sdst);
    asm volatile("cp.async.cg.shared.global [%0], [%1], 16;" :: "r"(s), "l"(gsrc));
}
__device__ __forceinline__ void cp_commit() {
    asm volatile("cp.async.commit_group;");
}
__device__ __forceinline__ void cp_wait0() {
    asm volatile("cp.async.wait_group 0;");
}

// ---------------------------------------------------------------------------
// Kernel A: logits = x @ clusters ; BN ; softmax(80) ; keep 64 (transposed out)
// Block 128x80, 8 warps (4Mx2N), warp 32x40. Double-buffered smem, one
// __syncthreads per chunk, register prefetch of next chunk.
// Dynamic smem layout (floats):
//   As[2][128][36] @ 0      (9216)
//   Bs[2][32][88]  @ 9216   (5632)   total 14848 floats = 59392 B
//   softmax overlay: Ls[128][81] @ 0, inv[128] @ 10368, red[256] @ 10496
// ---------------------------------------------------------------------------
#define ASSIGN_SMEM_BYTES 59392

__global__ __launch_bounds__(256, 2) void assign_kernel(
    const float* __restrict__ x,      // [32768, 512]
    const float* __restrict__ W,      // [512, 80]
    const float* __restrict__ bnw, const float* __restrict__ bnb,
    const float* __restrict__ bnm, const float* __restrict__ bnv)
{
    extern __shared__ float dyn[];
    float* AsBase = dyn;                 // [2][128][36]
    float* BsBase = dyn + 9216;          // [2][32][88]
    float (*Ls)[81] = reinterpret_cast<float(*)[81]>(dyn);
    float* invp = dyn + 10368;
    float* redp = dyn + 10496;
    __shared__ float s_sc[KC], s_tc[KC];

    const int t = threadIdx.x;
    const int lane = t & 31;
    const int wid = t >> 5;
    const int warpM = wid & 3;
    const int warpN = wid >> 2;
    const int g   = lane >> 2;
    const int tig = lane & 3;
    const int row0 = blockIdx.x * 128;

    if (t < KC) {
        float iv = rsqrtf(bnv[t] + 1e-5f);
        float sc = bnw[t] * iv;
        s_sc[t] = sc;
        s_tc[t] = bnb[t] - bnm[t] * sc;
    }

    float acc[2][5][4];
#pragma unroll
    for (int a = 0; a < 2; a++)
#pragma unroll
        for (int b = 0; b < 5; b++)
#pragma unroll
            for (int c = 0; c < 4; c++) acc[a][b][c] = 0.f;

    float4 pa[4];
    float4 pb[3];
    const int ar = t >> 3, ac4 = (t & 7) << 2;

    // prologue: LDG chunk 0
#pragma unroll
    for (int j = 0; j < 4; j++)
        pa[j] = *reinterpret_cast<const float4*>(
            &x[(size_t)(row0 + ar + j * 32) * Dd + ac4]);
#pragma unroll
    for (int j = 0; j < 3; j++) {
        int i = t + j * 256;
        if (i < 640)
            pb[j] = *reinterpret_cast<const float4*>(
                &W[(size_t)(i / 20) * KC + ((i % 20) << 2)]);
    }

    for (int c = 0; c < 16; c++) {
        const int p = c & 1;
        float* As = AsBase + p * (128 * 36);
        float* Bs = BsBase + p * (32 * 88);

        // STS current chunk (tf32 round)
#pragma unroll
        for (int j = 0; j < 4; j++) {
            float* dst = As + (ar + j * 32) * 36 + ac4;
            dst[0] = to_tf32(pa[j].x); dst[1] = to_tf32(pa[j].y);
            dst[2] = to_tf32(pa[j].z); dst[3] = to_tf32(pa[j].w);
        }
#pragma unroll
        for (int j = 0; j < 3; j++) {
            int i = t + j * 256;
            if (i < 640) {
                float* dst = Bs + (i / 20) * 88 + ((i % 20) << 2);
                dst[0] = to_tf32(pb[j].x); dst[1] = to_tf32(pb[j].y);
                dst[2] = to_tf32(pb[j].z); dst[3] = to_tf32(pb[j].w);
            }
        }
        __syncthreads();

        // LDG next chunk while MMAs run
        if (c < 15) {
            const int kt = (c + 1) * 32;
#pragma unroll
            for (int j = 0; j < 4; j++)
                pa[j] = *reinterpret_cast<const float4*>(
                    &x[(size_t)(row0 + ar + j * 32) * Dd + kt + ac4]);
#pragma unroll
            for (int j = 0; j < 3; j++) {
                int i = t + j * 256;
                if (i < 640)
                    pb[j] = *reinterpret_cast<const float4*>(
                        &W[(size_t)(kt + i / 20) * KC + ((i % 20) << 2)]);
            }
        }

        // MMA phase
#pragma unroll
        for (int ks = 0; ks < 4; ks++) {
            const int kk = ks << 3;
            uint32_t af[2][4];
#pragma unroll
            for (int mf = 0; mf < 2; mf++) {
                const int rb = warpM * 32 + mf * 16 + g;
                af[mf][0] = __float_as_uint(As[(rb    ) * 36 + kk + tig    ]);
                af[mf][1] = __float_as_uint(As[(rb + 8) * 36 + kk + tig    ]);
                af[mf][2] = __float_as_uint(As[(rb    ) * 36 + kk + tig + 4]);
                af[mf][3] = __float_as_uint(As[(rb + 8) * 36 + kk + tig + 4]);
            }
#pragma unroll
            for (int nf = 0; nf < 5; nf++) {
                const int cb = warpN * 40 + nf * 8 + g;
                uint32_t b0 = __float_as_uint(Bs[(kk + tig    ) * 88 + cb]);
                uint32_t b1 = __float_as_uint(Bs[(kk + tig + 4) * 88 + cb]);
                mma8(acc[0][nf], af[0], b0, b1);
                mma8(acc[1][nf], af[1], b0, b1);
            }
        }
    }
    __syncthreads();   // buffers dead; softmax overlay begins

    // BN fold + stage logits
#pragma unroll
    for (int mf = 0; mf < 2; mf++)
#pragma unroll
        for (int nf = 0; nf < 5; nf++)
#pragma unroll
            for (int c = 0; c < 4; c++) {
                int row = warpM * 32 + mf * 16 + g + ((c >> 1) << 3);
                int col = warpN * 40 + nf * 8 + 2 * tig + (c & 1);
                Ls[row][col] = fmaf(acc[mf][nf][c], s_sc[col], s_tc[col]);
            }
    __syncthreads();

    if (t < 128) {
        float m = -1e30f;
#pragma unroll
        for (int j = 0; j < KC; j++) m = fmaxf(m, Ls[t][j]);
        float ssum = 0.f;
#pragma unroll
        for (int j = 0; j < KC; j++) {
            float e = __expf(Ls[t][j] - m);
            ssum += e;
            if (j < Kk) Ls[t][j] = e;
        }
        invp[t] = 1.f / ssum;
    }
    __syncthreads();

    // transposed, tf32-rounded store: g_assign[(b*64+k)*1024 + n]
    const int bidx = row0 >> 10;       // batch
    const int nbase = row0 & 1023;
#pragma unroll
    for (int i = t; i < 128 * Kk; i += 256) {
        int k = i >> 7, r = i & 127;
        float e = Ls[r][k] * invp[r];
        g_assign[((size_t)bidx * Kk + k) * Nn + nbase + r] = to_tf32(e);
    }

    // per-column partial sums (k fixed per thread in this mapping)
    float partial = 0.f;
#pragma unroll
    for (int i = t; i < 128 * Kk; i += 256) {
        int r = i >> 6, k = i & 63;
        partial += Ls[r][k] * invp[r];
    }
    redp[t] = partial;
    __syncthreads();
    if (t < 64)
        g_asum_part[blockIdx.x * Kk + t] =
            redp[t] + redp[t + 64] + redp[t + 128] + redp[t + 192];
}

// ---------------------------------------------------------------------------
// Kernel B: O[k][d] = sum_n aT[k,n]*x[n,d] - asum[k]*c2[d,k]
// Block 64k x 64d, 128 threads, 4 warps (2Mk x 2Nd), warp 32x32.
// aT via cp.async (pre-rounded), x via LDG+cvt+STS. Double-buffered,
// one __syncthreads per chunk.
// ---------------------------------------------------------------------------
__global__ __launch_bounds__(128, 4) void vlad_kernel(
    const float* __restrict__ x,     // [32768, 512]
    const float* __restrict__ c2,    // [512, 64]
    float* __restrict__ out)         // [32, 512*64]
{
    __shared__ float aT_s[2][64][36];
    __shared__ float x_s[2][32][72];
    __shared__ float asum_s[64];
    __shared__ float redsq[4];

    const int t = threadIdx.x;
    const int lane = t & 31;
    const int wid = t >> 5;
    const int warpM = wid & 1;        // k stripe (32)
    const int warpN = wid >> 1;       // d stripe (32)
    const int g   = lane >> 2;
    const int tig = lane & 3;
    const int b  = blockIdx.y;
    const int d0 = blockIdx.x * 64;

    if (t < 64) {
        float s = 0.f;
#pragma unroll
        for (int j = 0; j < 8; j++)
            s += g_asum_part[((b << 3) + j) * Kk + t];
        asum_s[t] = s;
    }

    float acc[2][4][4];
#pragma unroll
    for (int mf = 0; mf < 2; mf++)
#pragma unroll
        for (int nf = 0; nf < 4; nf++)
#pragma unroll
            for (int c = 0; c < 4; c++) acc[mf][nf][c] = 0.f;

    const float* xb  = x + (size_t)b * Nn * Dd + d0;
    const float* abT = g_assign + (size_t)b * Kk * Nn;

    const int xn = t >> 4, xq = (t & 15) << 2;  // x tile thread map
    const int ak = t >> 1, aseg = (t & 1) << 2; // a tile: wrong—recompute below
    (void)ak; (void)aseg;
    float4 px[4];

    // prologue: cp.async a(0) -> buf0 ; LDG x(0) -> regs
#pragma unroll
    for (int j = 0; j < 4; j++) {
        int i = t + j * 128;               // 512 segs: k = i>>3, seg = i&7
        int k = i >> 3, seg = i & 7;
        cp16(&aT_s[0][k][seg << 2], abT + (size_t)k * Nn + (seg << 2));
    }
    cp_commit();
#pragma unroll
    for (int j = 0; j < 4; j++)
        px[j] = *reinterpret_cast<const float4*>(&xb[(size_t)(xn + j * 8) * Dd + xq]);

    for (int c = 0; c < 32; c++) {
        const int p = c & 1;

        cp_wait0();                        // a(c) resident in buf p
        // STS x(c) with tf32 round
#pragma unroll
        for (int j = 0; j < 4; j++) {
            float* dst = &x_s[p][xn + j * 8][xq];
            dst[0] = to_tf32(px[j].x); dst[1] = to_tf32(px[j].y);
            dst[2] = to_tf32(px[j].z); dst[3] = to_tf32(px[j].w);
        }
        __syncthreads();

        if (c < 31) {
            const int n1 = (c + 1) * 32;
#pragma unroll
            for (int j = 0; j < 4; j++) {
                int i = t + j * 128;
                int k = i >> 3, seg = i & 7;
                cp16(&aT_s[1 - p][k][seg << 2],
                     abT + (size_t)k * Nn + n1 + (seg << 2));
            }
            cp_commit();
#pragma unroll
            for (int j = 0; j < 4; j++)
                px[j] = *reinterpret_cast<const float4*>(
                    &xb[(size_t)(n1 + xn + j * 8) * Dd + xq]);
        }

        // MMA phase
#pragma unroll
        for (int ks = 0; ks < 4; ks++) {
            const int kk = ks << 3;
            uint32_t af[2][4];
#pragma unroll
            for (int mf = 0; mf < 2; mf++) {
                const int rb = warpM * 32 + mf * 16 + g;
                af[mf][0] = __float_as_uint(aT_s[p][rb    ][kk + tig    ]);
                af[mf][1] = __float_as_uint(aT_s[p][rb + 8][kk + tig    ]);
                af[mf][2] = __float_as_uint(aT_s[p][rb    ][kk + tig + 4]);
                af[mf][3] = __float_as_uint(aT_s[p][rb + 8][kk + tig + 4]);
            }
#pragma unroll
            for (int nf = 0; nf < 4; nf++) {
                const int cb = warpN * 32 + nf * 8 + g;
                uint32_t b0 = __float_as_uint(x_s[p][kk + tig    ][cb]);
                uint32_t b1 = __float_as_uint(x_s[p][kk + tig + 4][cb]);
                mma8(acc[0][nf], af[0], b0, b1);
                mma8(acc[1][nf], af[1], b0, b1);
            }
        }
    }

    // epilogue: rank-1 correction + store + sumsq partial
    float* ob = out + (size_t)b * (Dd * Kk);
    float ssq = 0.f;
#pragma unroll
    for (int mf = 0; mf < 2; mf++)
#pragma unroll
        for (int nf = 0; nf < 4; nf++)
#pragma unroll
            for (int c = 0; c < 4; c++) {
                int k = warpM * 32 + mf * 16 + g + ((c >> 1) << 3);
                int d = d0 + warpN * 32 + nf * 8 + 2 * tig + (c & 1);
                float v = acc[mf][nf][c] - asum_s[k] * c2[(size_t)d * Kk + k];
                ob[(size_t)d * Kk + k] = v;
                ssq = fmaf(v, v, ssq);
            }
#pragma unroll
    for (int off = 16; off > 0; off >>= 1)
        ssq += __shfl_xor_sync(0xffffffffu, ssq, off);
    if (lane == 0) redsq[wid] = ssq;
    __syncthreads();
    if (t == 0)
        g_ssq_part[b * 8 + blockIdx.x] = redsq[0] + redsq[1] + redsq[2] + redsq[3];
}

// ---------------------------------------------------------------------------
// Kernel C: pure scale pass (composed double L2-normalize)
// ---------------------------------------------------------------------------
__global__ __launch_bounds__(1024) void norm_kernel(float* __restrict__ out)
{
    const int b = blockIdx.x;
    const int t = threadIdx.x;
    __shared__ float scale_s;

    if (t == 0) {
        float v = 0.f;
#pragma unroll
        for (int j = 0; j < 8; j++) v += g_ssq_part[b * 8 + j];
        float s1 = v + 1e-12f;
        float n1 = sqrtf(s1);
        float s2 = v / s1 + 1e-12f;
        scale_s = 1.f / (n1 * sqrtf(s2));
    }
    __syncthreads();

    float sc = scale_s;
    float4* p = reinterpret_cast<float4*>(out + (size_t)b * (Dd * Kk));
#pragma unroll 4
    for (int i = t; i < 8192; i += 1024) {
        float4 v = p[i];
        v.x *= sc; v.y *= sc; v.z *= sc; v.w *= sc;
        p[i] = v;
    }
}

// ---------------------------------------------------------------------------
extern "C" void kernel_launch(void* const* d_in, const int* in_sizes, int n_in,
                              void* d_out, int out_size)
{
    const float* x   = (const float*)d_in[0];
    const float* W   = (const float*)d_in[1];
    const float* c2  = (const float*)d_in[2];
    const float* bnw = (const float*)d_in[3];
    const float* bnb = (const float*)d_in[4];
    const float* bnm = (const float*)d_in[5];
    const float* bnv = (const float*)d_in[6];
    float* out = (float*)d_out;

    cudaFuncSetAttribute(assign_kernel,
                         cudaFuncAttributeMaxDynamicSharedMemorySize,
                         ASSIGN_SMEM_BYTES);

    assign_kernel<<<ROWS / 128, 256, ASSIGN_SMEM_BYTES>>>(x, W, bnw, bnb, bnm, bnv);
    vlad_kernel<<<dim3(Dd / 64, Bb), 128>>>(x, c2, out);
    norm_kernel<<<Bb, 1024>>>(out);
}